// round 6
// baseline (speedup 1.0000x reference)
#include <cuda_runtime.h>
#include <math.h>
#include <stdint.h>

// Problem constants
#define DIMC   1024
#define HEADS  16
#define HDIM   64
#define BATCH  2
#define SEQ    2048
#define ROWS   (BATCH*SEQ)          // 4096
#define QKVC   (3*DIMC)             // 3072

// ---------------- scratch (static device memory; no cudaMalloc allowed) ----
__device__ float g_qkv [ROWS * QKVC];            // x @ Wqkv          (48 MB)
__device__ float g_q   [BATCH*HEADS*SEQ*HDIM];   // [B,H,N,HD] rope'd+scaled
__device__ float g_k   [BATCH*HEADS*SEQ*HDIM];
__device__ float g_v   [BATCH*HEADS*SEQ*HDIM];
__device__ float g_attn[ROWS * DIMC];            // attention out [B,N,DIM]

// ============================================================================
// Kernel 1/4: fp32 SGEMM  C[M,N] = A[M,K] @ B[K,N] (+ bias)
// 128x128 block tile, BK=8, 256 threads, 8x8 per-thread microtile.
// Software-pipelined: next tile's global loads are prefetched into registers
// before the FFMA block, stored to smem after the trailing sync.
// All dims are multiples of the tile sizes (4096/3072/1024) — no guards.
// ============================================================================
__global__ __launch_bounds__(256)
void sgemm_kernel(const float* __restrict__ A, const float* __restrict__ B,
                  float* __restrict__ C, int M, int N, int K,
                  const float* __restrict__ bias)
{
    const int BM = 128, BN = 128, BK = 8, TM = 8, TN = 8;
    __shared__ float As[BK][BM];   // transposed A tile
    __shared__ float Bs[BK][BN];

    int tid  = threadIdx.x;
    int brow = blockIdx.y * BM;
    int bcol = blockIdx.x * BN;
    int trow = (tid / 16) * TM;
    int tcol = (tid % 16) * TN;

    // global->smem load mapping (one float4 per thread per tile each)
    int aRow = tid >> 1;                 // 0..127
    int aCol = (tid & 1) * 4;            // 0 or 4
    int bRow = tid >> 5;                 // 0..7
    int bCol = (tid & 31) * 4;           // 0..124

    const float* Abase = A + (size_t)(brow + aRow) * K + aCol;
    const float* Bbase = B + (size_t)bRow * N + bcol + bCol;

    float acc[TM][TN];
    #pragma unroll
    for (int i = 0; i < TM; i++)
        #pragma unroll
        for (int j = 0; j < TN; j++) acc[i][j] = 0.f;

    // prologue: first tile into registers, then smem
    float4 av = *(const float4*)(Abase);
    float4 bv = *(const float4*)(Bbase);

    for (int k0 = 0; k0 < K; k0 += BK) {
        As[aCol+0][aRow] = av.x;
        As[aCol+1][aRow] = av.y;
        As[aCol+2][aRow] = av.z;
        As[aCol+3][aRow] = av.w;
        *(float4*)&Bs[bRow][bCol] = bv;
        __syncthreads();

        // prefetch next tile while computing this one
        if (k0 + BK < K) {
            av = *(const float4*)(Abase + (k0 + BK));
            bv = *(const float4*)(Bbase + (size_t)(k0 + BK) * N);
        }

        #pragma unroll
        for (int kk = 0; kk < BK; kk++) {
            float ar[TM], br[TN];
            *(float4*)&ar[0] = *(const float4*)&As[kk][trow];
            *(float4*)&ar[4] = *(const float4*)&As[kk][trow + 4];
            *(float4*)&br[0] = *(const float4*)&Bs[kk][tcol];
            *(float4*)&br[4] = *(const float4*)&Bs[kk][tcol + 4];
            #pragma unroll
            for (int i = 0; i < TM; i++)
                #pragma unroll
                for (int j = 0; j < TN; j++)
                    acc[i][j] += ar[i] * br[j];
        }
        __syncthreads();
    }

    #pragma unroll
    for (int i = 0; i < TM; i++) {
        size_t r = (size_t)(brow + trow + i);
        #pragma unroll
        for (int j = 0; j < TN; j += 4) {
            int c = bcol + tcol + j;
            float4 v;
            v.x = acc[i][j+0]; v.y = acc[i][j+1];
            v.z = acc[i][j+2]; v.w = acc[i][j+3];
            if (bias) {
                v.x += bias[c+0]; v.y += bias[c+1];
                v.z += bias[c+2]; v.w += bias[c+3];
            }
            *(float4*)(C + r * N + c) = v;
        }
    }
}

// ============================================================================
// Kernel 2: per-head LayerNorm + RoPE + scatter to [B,H,N,HD].
// One warp handles one (b,n,h) row; lane owns the RoPE pair (2*lane, 2*lane+1).
// Q is pre-scaled by 1/sqrt(HD)=0.125 so attention needs no scale.
// ============================================================================
__global__ __launch_bounds__(256)
void lnrope_kernel(const float* __restrict__ freq,
                   const float* __restrict__ qg, const float* __restrict__ qb,
                   const float* __restrict__ kg, const float* __restrict__ kb)
{
    int warp = (blockIdx.x * blockDim.x + threadIdx.x) >> 5;
    int lane = threadIdx.x & 31;
    const int TOTAL = BATCH * SEQ * HEADS;
    if (warp >= TOTAL) return;

    int h = warp & (HEADS - 1);
    int n = (warp >> 4) & (SEQ - 1);
    int b = warp >> 15;                       // SEQ*HEADS = 2^15

    const float* src = g_qkv + (size_t)(b * SEQ + n) * QKVC + h * HDIM;
    int d0 = lane * 2;

    float2 q2 = *(const float2*)(src + d0);
    float2 k2 = *(const float2*)(src + DIMC + d0);
    float2 v2 = *(const float2*)(src + 2 * DIMC + d0);

    // LayerNorm over HD=64 for q and k (warp reduce of sum / sumsq)
    float sq  = q2.x + q2.y,           sk  = k2.x + k2.y;
    float sq2 = q2.x*q2.x + q2.y*q2.y, sk2 = k2.x*k2.x + k2.y*k2.y;
    #pragma unroll
    for (int off = 16; off; off >>= 1) {
        sq  += __shfl_xor_sync(0xffffffffu, sq,  off);
        sq2 += __shfl_xor_sync(0xffffffffu, sq2, off);
        sk  += __shfl_xor_sync(0xffffffffu, sk,  off);
        sk2 += __shfl_xor_sync(0xffffffffu, sk2, off);
    }
    float qm = sq * (1.f/64.f);
    float qv = sq2 * (1.f/64.f) - qm * qm;
    float qi = rsqrtf(qv + 1e-5f);
    float km = sk * (1.f/64.f);
    float kv = sk2 * (1.f/64.f) - km * km;
    float ki = rsqrtf(kv + 1e-5f);

    float qn0 = (q2.x - qm) * qi * qg[d0]     + qb[d0];
    float qn1 = (q2.y - qm) * qi * qg[d0 + 1] + qb[d0 + 1];
    float kn0 = (k2.x - km) * ki * kg[d0]     + kb[d0];
    float kn1 = (k2.y - km) * ki * kg[d0 + 1] + kb[d0 + 1];

    // RoPE: lane = pair index j; freq_cis[n, j, {cos,sin}]
    float co = freq[(n * 32 + lane) * 2 + 0];
    float si = freq[(n * 32 + lane) * 2 + 1];
    float qr = (qn0 * co - qn1 * si) * 0.125f;
    float qe = (qn0 * si + qn1 * co) * 0.125f;
    float kr =  kn0 * co - kn1 * si;
    float ke =  kn0 * si + kn1 * co;

    size_t o = ((size_t)(b * HEADS + h) * SEQ + n) * HDIM + d0;
    *(float2*)(g_q + o) = make_float2(qr, qe);
    *(float2*)(g_k + o) = make_float2(kr, ke);
    *(float2*)(g_v + o) = v2;
}

// ============================================================================
// Kernel 3: flash attention, fp32.
// Block = 64 Q-rows of one (b,h). 256 threads as 16x16; each thread owns a
// 4x4 microtile of S and of the 64x64 output accumulator. K/V streamed in
// 64-key tiles; the K smem buffer (stored d-major) is reused to hold P.
// ============================================================================
__global__ __launch_bounds__(256)
void attn_kernel()
{
    __shared__ float Qs [HDIM][64];   // Q tile, d-major: Qs[d][row]
    __shared__ float KPs[64][64];     // K tile d-major Ks[d][key]; reused as P[row][key]
    __shared__ float Vs [64][HDIM];   // V tile natural: Vs[key][d]

    int qt = blockIdx.x;              // 0..31 q tile
    int bh = blockIdx.y;              // 0..31  (b*16 + h)
    int tid = threadIdx.x;
    int ty = tid >> 4, tx = tid & 15;

    const float* Qb = g_q + ((size_t)bh * SEQ + qt * 64) * HDIM;
    const float* Kb = g_k + (size_t)bh * SEQ * HDIM;
    const float* Vb = g_v + (size_t)bh * SEQ * HDIM;

    // Load Q tile transposed into Qs[d][row]
    #pragma unroll
    for (int i = tid; i < 64 * 16; i += 256) {
        int r  = i >> 4;
        int d4 = (i & 15) * 4;
        float4 v = *(const float4*)(Qb + r * HDIM + d4);
        Qs[d4+0][r] = v.x; Qs[d4+1][r] = v.y;
        Qs[d4+2][r] = v.z; Qs[d4+3][r] = v.w;
    }

    float m_prev[4], l_prev[4], acc[4][4];
    #pragma unroll
    for (int i = 0; i < 4; i++) {
        m_prev[i] = -INFINITY; l_prev[i] = 0.f;
        #pragma unroll
        for (int j = 0; j < 4; j++) acc[i][j] = 0.f;
    }

    for (int kt = 0; kt < SEQ / 64; kt++) {
        // Load K (transposed) and V tiles
        const float* Kt = Kb + kt * 64 * HDIM;
        const float* Vt = Vb + kt * 64 * HDIM;
        #pragma unroll
        for (int i = tid; i < 64 * 16; i += 256) {
            int r  = i >> 4;
            int d4 = (i & 15) * 4;
            float4 kvv = *(const float4*)(Kt + r * HDIM + d4);
            KPs[d4+0][r] = kvv.x; KPs[d4+1][r] = kvv.y;
            KPs[d4+2][r] = kvv.z; KPs[d4+3][r] = kvv.w;
            *(float4*)&Vs[r][d4] = *(const float4*)(Vt + r * HDIM + d4);
        }
        __syncthreads();

        // S = Q @ K^T  (q pre-scaled by 1/sqrt(64))
        float s[4][4];
        #pragma unroll
        for (int i = 0; i < 4; i++)
            #pragma unroll
            for (int j = 0; j < 4; j++) s[i][j] = 0.f;
        #pragma unroll 8
        for (int kk = 0; kk < HDIM; kk++) {
            float a[4], bb[4];
            *(float4*)a  = *(const float4*)&Qs [kk][ty * 4];
            *(float4*)bb = *(const float4*)&KPs[kk][tx * 4];
            #pragma unroll
            for (int i = 0; i < 4; i++)
                #pragma unroll
                for (int j = 0; j < 4; j++)
                    s[i][j] += a[i] * bb[j];
        }

        // online softmax update; row-group = 16 lanes sharing ty (lane-aligned:
        // shuffle offsets <= 8 stay inside the 16-lane half-warp of a row)
        float mnew[4], alpha[4], lloc[4];
        #pragma unroll
        for (int i = 0; i < 4; i++) {
            float m = fmaxf(fmaxf(s[i][0], s[i][1]), fmaxf(s[i][2], s[i][3]));
            #pragma unroll
            for (int off = 8; off; off >>= 1)
                m = fmaxf(m, __shfl_xor_sync(0xffffffffu, m, off));
            mnew[i]  = fmaxf(m_prev[i], m);
            alpha[i] = __expf(m_prev[i] - mnew[i]);
            float ls = 0.f;
            #pragma unroll
            for (int j = 0; j < 4; j++) {
                s[i][j] = __expf(s[i][j] - mnew[i]);
                ls += s[i][j];
            }
            #pragma unroll
            for (int off = 8; off; off >>= 1)
                ls += __shfl_xor_sync(0xffffffffu, ls, off);
            lloc[i] = ls;
        }
        __syncthreads();   // everyone done reading KPs as K

        // stash P (=s) into the K buffer, row-major [row][key]
        #pragma unroll
        for (int i = 0; i < 4; i++) {
            float4 p4; p4.x = s[i][0]; p4.y = s[i][1]; p4.z = s[i][2]; p4.w = s[i][3];
            *(float4*)&KPs[ty * 4 + i][tx * 4] = p4;
        }
        // rescale accumulators + running stats
        #pragma unroll
        for (int i = 0; i < 4; i++) {
            l_prev[i] = alpha[i] * l_prev[i] + lloc[i];
            m_prev[i] = mnew[i];
            #pragma unroll
            for (int j = 0; j < 4; j++) acc[i][j] *= alpha[i];
        }
        __syncthreads();   // P visible

        // acc += P @ V
        #pragma unroll 4
        for (int kk = 0; kk < 64; kk += 4) {
            float pr[4][4];
            #pragma unroll
            for (int i = 0; i < 4; i++)
                *(float4*)pr[i] = *(const float4*)&KPs[ty * 4 + i][kk];
            #pragma unroll
            for (int kc = 0; kc < 4; kc++) {
                float v4[4];
                *(float4*)v4 = *(const float4*)&Vs[kk + kc][tx * 4];
                #pragma unroll
                for (int i = 0; i < 4; i++)
                    #pragma unroll
                    for (int j = 0; j < 4; j++)
                        acc[i][j] += pr[i][kc] * v4[j];
            }
        }
        __syncthreads();   // done reading KPs/Vs before next tile load
    }

    // epilogue: divide by l, write straight into [B, N, DIM] layout
    int b = bh >> 4, h = bh & 15;
    #pragma unroll
    for (int i = 0; i < 4; i++) {
        float inv = 1.f / l_prev[i];
        int n = qt * 64 + ty * 4 + i;
        float4 o;
        o.x = acc[i][0] * inv; o.y = acc[i][1] * inv;
        o.z = acc[i][2] * inv; o.w = acc[i][3] * inv;
        *(float4*)(g_attn + (size_t)(b * SEQ + n) * DIMC + h * HDIM + tx * 4) = o;
    }
}

// ============================================================================
// launch
// ============================================================================
extern "C" void kernel_launch(void* const* d_in, const int* in_sizes, int n_in,
                              void* d_out, int out_size)
{
    const float* x    = (const float*)d_in[0];
    const float* freq = (const float*)d_in[1];
    const float* Wqkv = (const float*)d_in[2];
    const float* qg   = (const float*)d_in[3];
    const float* qb   = (const float*)d_in[4];
    const float* kg   = (const float*)d_in[5];
    const float* kb   = (const float*)d_in[6];
    const float* Wp   = (const float*)d_in[7];
    const float* bp   = (const float*)d_in[8];
    float* out = (float*)d_out;

    float *qkv_p = nullptr, *attn_p = nullptr;
    cudaGetSymbolAddress((void**)&qkv_p,  g_qkv);   // not a stream op; capture-safe
    cudaGetSymbolAddress((void**)&attn_p, g_attn);

    // 1. qkv = x @ Wqkv          [4096,1024] @ [1024,3072]
    {
        dim3 grid(QKVC / 128, ROWS / 128);
        sgemm_kernel<<<grid, 256>>>(x, Wqkv, qkv_p, ROWS, QKVC, DIMC, nullptr);
    }
    // 2. LN + RoPE + scatter to [B,H,N,HD] (Q pre-scaled by 1/8)
    {
        int warps = BATCH * SEQ * HEADS;            // 65536
        lnrope_kernel<<<warps / 8, 256>>>(freq, qg, qb, kg, kb);
    }
    // 3. flash attention -> g_attn [B,N,DIM]
    {
        dim3 grid(SEQ / 64, BATCH * HEADS);
        attn_kernel<<<grid, 256>>>();
    }
    // 4. out = attn @ Wproj + bproj   [4096,1024] @ [1024,1024]
    {
        dim3 grid(DIMC / 128, ROWS / 128);
        sgemm_kernel<<<grid, 256>>>(attn_p, Wp, out, ROWS, DIMC, DIMC, bp);
    }
}

// round 9
// speedup vs baseline: 1.3593x; 1.3593x over previous
// build-id: r9-tf32-gemm-resubmit (content delta vs r7/r8 to bust any poisoned build cache)
#include <cuda_runtime.h>
#include <math.h>
#include <stdint.h>

// Problem constants
#define DIMC   1024
#define HEADS  16
#define HDIM   64
#define BATCH  2
#define SEQ    2048
#define ROWS   (BATCH*SEQ)          // 4096
#define QKVC   (3*DIMC)             // 3072

// ---------------- scratch (static device memory; no cudaMalloc allowed) ----
__device__ float g_qkv [ROWS * QKVC];            // x @ Wqkv
__device__ float g_q   [BATCH*HEADS*SEQ*HDIM];   // [B,H,N,HD] rope'd+scaled
__device__ float g_k   [BATCH*HEADS*SEQ*HDIM];
__device__ float g_v   [BATCH*HEADS*SEQ*HDIM];
__device__ float g_attn[ROWS * DIMC];            // attention out [B,N,DIM]

// ============================================================================
// tf32 mma helpers
// ============================================================================
__device__ __forceinline__ uint32_t f2tf32(float x) {
    uint32_t r;
    asm("cvt.rna.tf32.f32 %0, %1;" : "=r"(r) : "f"(x));
    return r;
}

__device__ __forceinline__ void mma_tf32(float d[4], const uint32_t a[4],
                                         const uint32_t b[2]) {
    asm volatile(
        "mma.sync.aligned.m16n8k8.row.col.f32.tf32.tf32.f32 "
        "{%0,%1,%2,%3}, {%4,%5,%6,%7}, {%8,%9}, {%0,%1,%2,%3};"
        : "+f"(d[0]), "+f"(d[1]), "+f"(d[2]), "+f"(d[3])
        : "r"(a[0]), "r"(a[1]), "r"(a[2]), "r"(a[3]), "r"(b[0]), "r"(b[1]));
}

// ============================================================================
// Kernel 1/4: tf32 tensor-core GEMM  C[M,N] = A[M,K] @ B[K,N] (+ bias)
// Block 128x128x16, 256 threads = 8 warps in 2(m) x 4(n); warp tile 64x32.
// smem: As[k][m], Bs[k][n], tf32 bits, row pad 136 (136%32==8 makes all
// fragment LDS patterns hit 32 distinct banks). Register-prefetch pipelined.
// All dims are multiples of tile sizes (4096/3072/1024) — no guards.
// ============================================================================
#define GBK   16
#define GPAD  136

__global__ __launch_bounds__(256)
void mma_gemm_kernel(const float* __restrict__ A, const float* __restrict__ B,
                     float* __restrict__ C, int M, int N, int K,
                     const float* __restrict__ bias)
{
    __shared__ __align__(16) uint32_t As[GBK][GPAD];   // [k][m]
    __shared__ __align__(16) uint32_t Bs[GBK][GPAD];   // [k][n]

    int tid  = threadIdx.x;
    int warp = tid >> 5, lane = tid & 31;
    int g  = lane >> 2;          // groupID (row within fragment)
    int tg = lane & 3;           // thread-in-group (k / col pair)
    int wm = (warp >> 2) * 64;   // warp m offset
    int wn = (warp & 3) * 32;    // warp n offset

    int brow = blockIdx.y * 128;
    int bcol = blockIdx.x * 128;

    const float* Ab = A + (size_t)brow * K;   // A row-major [M][K]
    const float* Bb = B + bcol;               // B row-major [K][N]

    // global->reg load mapping (2 float4 each for A and B per tile):
    //  A: idx in [0,512): row = idx>>2, klocal = (idx&3)*4   (k-contiguous)
    //  B: idx in [0,512): klocal = idx>>5, nlocal = (idx&31)*4 (n-contiguous)
    float4 ra[2], rb[2];
    #pragma unroll
    for (int u = 0; u < 2; u++) {
        int ai = tid + u * 256;
        ra[u] = *(const float4*)(Ab + (size_t)(ai >> 2) * K + ((ai & 3) * 4));
        int bi = tid + u * 256;
        rb[u] = *(const float4*)(Bb + (size_t)(bi >> 5) * N + ((bi & 31) * 4));
    }

    float d[4][4][4];
    #pragma unroll
    for (int mi = 0; mi < 4; mi++)
        #pragma unroll
        for (int ni = 0; ni < 4; ni++)
            #pragma unroll
            for (int r = 0; r < 4; r++) d[mi][ni][r] = 0.f;

    for (int k0 = 0; k0 < K; k0 += GBK) {
        // stage regs -> smem (tf32 convert). A transposed (scalar), B vector.
        #pragma unroll
        for (int u = 0; u < 2; u++) {
            int ai = tid + u * 256;
            int ar = ai >> 2, ak = (ai & 3) * 4;
            As[ak + 0][ar] = f2tf32(ra[u].x);
            As[ak + 1][ar] = f2tf32(ra[u].y);
            As[ak + 2][ar] = f2tf32(ra[u].z);
            As[ak + 3][ar] = f2tf32(ra[u].w);
            int bi = tid + u * 256;
            int bk = bi >> 5, bn = (bi & 31) * 4;
            uint4 bw;
            bw.x = f2tf32(rb[u].x); bw.y = f2tf32(rb[u].y);
            bw.z = f2tf32(rb[u].z); bw.w = f2tf32(rb[u].w);
            *(uint4*)&Bs[bk][bn] = bw;
        }
        __syncthreads();

        // prefetch next tile while computing this one
        if (k0 + GBK < K) {
            #pragma unroll
            for (int u = 0; u < 2; u++) {
                int ai = tid + u * 256;
                ra[u] = *(const float4*)(Ab + (size_t)(ai >> 2) * K
                                            + (k0 + GBK + (ai & 3) * 4));
                int bi = tid + u * 256;
                rb[u] = *(const float4*)(Bb + (size_t)(k0 + GBK + (bi >> 5)) * N
                                            + ((bi & 31) * 4));
            }
        }

        #pragma unroll
        for (int ks = 0; ks < 2; ks++) {
            int kb = ks * 8;
            uint32_t af[4][4], bf[4][2];
            // A fragment: a0=[g][tg] a1=[g+8][tg] a2=[g][tg+4] a3=[g+8][tg+4]
            #pragma unroll
            for (int mi = 0; mi < 4; mi++) {
                int m0 = wm + mi * 16;
                af[mi][0] = As[kb + tg    ][m0 + g    ];
                af[mi][1] = As[kb + tg    ][m0 + g + 8];
                af[mi][2] = As[kb + tg + 4][m0 + g    ];
                af[mi][3] = As[kb + tg + 4][m0 + g + 8];
            }
            // B fragment: b0=[k=tg][n=g]  b1=[k=tg+4][n=g]
            #pragma unroll
            for (int ni = 0; ni < 4; ni++) {
                int n0 = wn + ni * 8;
                bf[ni][0] = Bs[kb + tg    ][n0 + g];
                bf[ni][1] = Bs[kb + tg + 4][n0 + g];
            }
            #pragma unroll
            for (int mi = 0; mi < 4; mi++)
                #pragma unroll
                for (int ni = 0; ni < 4; ni++)
                    mma_tf32(d[mi][ni], af[mi], bf[ni]);
        }
        __syncthreads();
    }

    // epilogue: c0=[g][2tg] c1=[g][2tg+1] c2=[g+8][2tg] c3=[g+8][2tg+1]
    #pragma unroll
    for (int mi = 0; mi < 4; mi++) {
        #pragma unroll
        for (int ni = 0; ni < 4; ni++) {
            int r0 = brow + wm + mi * 16 + g;
            int c  = bcol + wn + ni * 8 + 2 * tg;
            float2 v0, v1;
            v0.x = d[mi][ni][0]; v0.y = d[mi][ni][1];
            v1.x = d[mi][ni][2]; v1.y = d[mi][ni][3];
            if (bias) {
                float2 bb = *(const float2*)(bias + c);
                v0.x += bb.x; v0.y += bb.y;
                v1.x += bb.x; v1.y += bb.y;
            }
            *(float2*)(C + (size_t)r0 * N + c)       = v0;
            *(float2*)(C + (size_t)(r0 + 8) * N + c) = v1;
        }
    }
}

// ============================================================================
// Kernel 2: per-head LayerNorm + RoPE + scatter to [B,H,N,HD].  (unchanged)
// ============================================================================
__global__ __launch_bounds__(256)
void lnrope_kernel(const float* __restrict__ freq,
                   const float* __restrict__ qg, const float* __restrict__ qb,
                   const float* __restrict__ kg, const float* __restrict__ kb)
{
    int warp = (blockIdx.x * blockDim.x + threadIdx.x) >> 5;
    int lane = threadIdx.x & 31;
    const int TOTAL = BATCH * SEQ * HEADS;
    if (warp >= TOTAL) return;

    int h = warp & (HEADS - 1);
    int n = (warp >> 4) & (SEQ - 1);
    int b = warp >> 15;

    const float* src = g_qkv + (size_t)(b * SEQ + n) * QKVC + h * HDIM;
    int d0 = lane * 2;

    float2 q2 = *(const float2*)(src + d0);
    float2 k2 = *(const float2*)(src + DIMC + d0);
    float2 v2 = *(const float2*)(src + 2 * DIMC + d0);

    float sq  = q2.x + q2.y,           sk  = k2.x + k2.y;
    float sq2 = q2.x*q2.x + q2.y*q2.y, sk2 = k2.x*k2.x + k2.y*k2.y;
    #pragma unroll
    for (int off = 16; off; off >>= 1) {
        sq  += __shfl_xor_sync(0xffffffffu, sq,  off);
        sq2 += __shfl_xor_sync(0xffffffffu, sq2, off);
        sk  += __shfl_xor_sync(0xffffffffu, sk,  off);
        sk2 += __shfl_xor_sync(0xffffffffu, sk2, off);
    }
    float qm = sq * (1.f/64.f);
    float qv = sq2 * (1.f/64.f) - qm * qm;
    float qi = rsqrtf(qv + 1e-5f);
    float km = sk * (1.f/64.f);
    float kv = sk2 * (1.f/64.f) - km * km;
    float ki = rsqrtf(kv + 1e-5f);

    float qn0 = (q2.x - qm) * qi * qg[d0]     + qb[d0];
    float qn1 = (q2.y - qm) * qi * qg[d0 + 1] + qb[d0 + 1];
    float kn0 = (k2.x - km) * ki * kg[d0]     + kb[d0];
    float kn1 = (k2.y - km) * ki * kg[d0 + 1] + kb[d0 + 1];

    float co = freq[(n * 32 + lane) * 2 + 0];
    float si = freq[(n * 32 + lane) * 2 + 1];
    float qr = (qn0 * co - qn1 * si) * 0.125f;
    float qe = (qn0 * si + qn1 * co) * 0.125f;
    float kr =  kn0 * co - kn1 * si;
    float ke =  kn0 * si + kn1 * co;

    size_t o = ((size_t)(b * HEADS + h) * SEQ + n) * HDIM + d0;
    *(float2*)(g_q + o) = make_float2(qr, qe);
    *(float2*)(g_k + o) = make_float2(kr, ke);
    *(float2*)(g_v + o) = v2;
}

// ============================================================================
// Kernel 3: flash attention, fp32.  (unchanged — proven correct in R6)
// ============================================================================
__global__ __launch_bounds__(256)
void attn_kernel()
{
    __shared__ float Qs [HDIM][64];
    __shared__ float KPs[64][64];
    __shared__ float Vs [64][HDIM];

    int qt = blockIdx.x;
    int bh = blockIdx.y;
    int tid = threadIdx.x;
    int ty = tid >> 4, tx = tid & 15;

    const float* Qb = g_q + ((size_t)bh * SEQ + qt * 64) * HDIM;
    const float* Kb = g_k + (size_t)bh * SEQ * HDIM;
    const float* Vb = g_v + (size_t)bh * SEQ * HDIM;

    #pragma unroll
    for (int i = tid; i < 64 * 16; i += 256) {
        int r  = i >> 4;
        int d4 = (i & 15) * 4;
        float4 v = *(const float4*)(Qb + r * HDIM + d4);
        Qs[d4+0][r] = v.x; Qs[d4+1][r] = v.y;
        Qs[d4+2][r] = v.z; Qs[d4+3][r] = v.w;
    }

    float m_prev[4], l_prev[4], acc[4][4];
    #pragma unroll
    for (int i = 0; i < 4; i++) {
        m_prev[i] = -INFINITY; l_prev[i] = 0.f;
        #pragma unroll
        for (int j = 0; j < 4; j++) acc[i][j] = 0.f;
    }

    for (int kt = 0; kt < SEQ / 64; kt++) {
        const float* Kt = Kb + kt * 64 * HDIM;
        const float* Vt = Vb + kt * 64 * HDIM;
        #pragma unroll
        for (int i = tid; i < 64 * 16; i += 256) {
            int r  = i >> 4;
            int d4 = (i & 15) * 4;
            float4 kvv = *(const float4*)(Kt + r * HDIM + d4);
            KPs[d4+0][r] = kvv.x; KPs[d4+1][r] = kvv.y;
            KPs[d4+2][r] = kvv.z; KPs[d4+3][r] = kvv.w;
            *(float4*)&Vs[r][d4] = *(const float4*)(Vt + r * HDIM + d4);
        }
        __syncthreads();

        float s[4][4];
        #pragma unroll
        for (int i = 0; i < 4; i++)
            #pragma unroll
            for (int j = 0; j < 4; j++) s[i][j] = 0.f;
        #pragma unroll 8
        for (int kk = 0; kk < HDIM; kk++) {
            float a[4], bb[4];
            *(float4*)a  = *(const float4*)&Qs [kk][ty * 4];
            *(float4*)bb = *(const float4*)&KPs[kk][tx * 4];
            #pragma unroll
            for (int i = 0; i < 4; i++)
                #pragma unroll
                for (int j = 0; j < 4; j++)
                    s[i][j] += a[i] * bb[j];
        }

        float mnew[4], alpha[4], lloc[4];
        #pragma unroll
        for (int i = 0; i < 4; i++) {
            float m = fmaxf(fmaxf(s[i][0], s[i][1]), fmaxf(s[i][2], s[i][3]));
            #pragma unroll
            for (int off = 8; off; off >>= 1)
                m = fmaxf(m, __shfl_xor_sync(0xffffffffu, m, off));
            mnew[i]  = fmaxf(m_prev[i], m);
            alpha[i] = __expf(m_prev[i] - mnew[i]);
            float ls = 0.f;
            #pragma unroll
            for (int j = 0; j < 4; j++) {
                s[i][j] = __expf(s[i][j] - mnew[i]);
                ls += s[i][j];
            }
            #pragma unroll
            for (int off = 8; off; off >>= 1)
                ls += __shfl_xor_sync(0xffffffffu, ls, off);
            lloc[i] = ls;
        }
        __syncthreads();

        #pragma unroll
        for (int i = 0; i < 4; i++) {
            float4 p4; p4.x = s[i][0]; p4.y = s[i][1]; p4.z = s[i][2]; p4.w = s[i][3];
            *(float4*)&KPs[ty * 4 + i][tx * 4] = p4;
        }
        #pragma unroll
        for (int i = 0; i < 4; i++) {
            l_prev[i] = alpha[i] * l_prev[i] + lloc[i];
            m_prev[i] = mnew[i];
            #pragma unroll
            for (int j = 0; j < 4; j++) acc[i][j] *= alpha[i];
        }
        __syncthreads();

        #pragma unroll 4
        for (int kk = 0; kk < 64; kk += 4) {
            float pr[4][4];
            #pragma unroll
            for (int i = 0; i < 4; i++)
                *(float4*)pr[i] = *(const float4*)&KPs[ty * 4 + i][kk];
            #pragma unroll
            for (int kc = 0; kc < 4; kc++) {
                float v4[4];
                *(float4*)v4 = *(const float4*)&Vs[kk + kc][tx * 4];
                #pragma unroll
                for (int i = 0; i < 4; i++)
                    #pragma unroll
                    for (int j = 0; j < 4; j++)
                        acc[i][j] += pr[i][kc] * v4[j];
            }
        }
        __syncthreads();
    }

    int b = bh >> 4, h = bh & 15;
    #pragma unroll
    for (int i = 0; i < 4; i++) {
        float inv = 1.f / l_prev[i];
        int n = qt * 64 + ty * 4 + i;
        float4 o;
        o.x = acc[i][0] * inv; o.y = acc[i][1] * inv;
        o.z = acc[i][2] * inv; o.w = acc[i][3] * inv;
        *(float4*)(g_attn + (size_t)(b * SEQ + n) * DIMC + h * HDIM + tx * 4) = o;
    }
}

// ============================================================================
// launch
// ============================================================================
extern "C" void kernel_launch(void* const* d_in, const int* in_sizes, int n_in,
                              void* d_out, int out_size)
{
    const float* x    = (const float*)d_in[0];
    const float* freq = (const float*)d_in[1];
    const float* Wqkv = (const float*)d_in[2];
    const float* qg   = (const float*)d_in[3];
    const float* qb   = (const float*)d_in[4];
    const float* kg   = (const float*)d_in[5];
    const float* kb   = (const float*)d_in[6];
    const float* Wp   = (const float*)d_in[7];
    const float* bp   = (const float*)d_in[8];
    float* out = (float*)d_out;

    float *qkv_p = nullptr, *attn_p = nullptr;
    cudaGetSymbolAddress((void**)&qkv_p,  g_qkv);
    cudaGetSymbolAddress((void**)&attn_p, g_attn);

    // 1. qkv = x @ Wqkv          [4096,1024] @ [1024,3072]  (tf32 mma)
    {
        dim3 grid(QKVC / 128, ROWS / 128);
        mma_gemm_kernel<<<grid, 256>>>(x, Wqkv, qkv_p, ROWS, QKVC, DIMC, nullptr);
    }
    // 2. LN + RoPE + scatter to [B,H,N,HD] (Q pre-scaled by 1/8)
    {
        int warps = BATCH * SEQ * HEADS;
        lnrope_kernel<<<warps / 8, 256>>>(freq, qg, qb, kg, kb);
    }
    // 3. flash attention -> g_attn [B,N,DIM]
    {
        dim3 grid(SEQ / 64, BATCH * HEADS);
        attn_kernel<<<grid, 256>>>();
    }
    // 4. out = attn @ Wproj + bproj   [4096,1024] @ [1024,1024]  (tf32 mma)
    {
        dim3 grid(DIMC / 128, ROWS / 128);
        mma_gemm_kernel<<<grid, 256>>>(attn_p, Wp, out, ROWS, DIMC, DIMC, bp);
    }
}

// round 13
// speedup vs baseline: 2.2998x; 1.6919x over previous
// build-id: r10-attn-mma
#include <cuda_runtime.h>
#include <math.h>
#include <stdint.h>

// Problem constants
#define DIMC   1024
#define HEADS  16
#define HDIM   64
#define BATCH  2
#define SEQ    2048
#define ROWS   (BATCH*SEQ)          // 4096
#define QKVC   (3*DIMC)             // 3072

// ---------------- scratch (static device memory; no cudaMalloc allowed) ----
__device__ float g_qkv [ROWS * QKVC];            // x @ Wqkv
__device__ float g_q   [BATCH*HEADS*SEQ*HDIM];   // [B,H,N,HD] rope'd+scaled
__device__ float g_k   [BATCH*HEADS*SEQ*HDIM];
__device__ float g_v   [BATCH*HEADS*SEQ*HDIM];
__device__ float g_attn[ROWS * DIMC];            // attention out [B,N,DIM]

// ============================================================================
// tf32 mma helpers (validated in R9: fragment mapping passed at rel_err 5.7e-4)
// ============================================================================
__device__ __forceinline__ uint32_t f2tf32(float x) {
    uint32_t r;
    asm("cvt.rna.tf32.f32 %0, %1;" : "=r"(r) : "f"(x));
    return r;
}

__device__ __forceinline__ void mma_tf32(float d[4], const uint32_t a[4],
                                         const uint32_t b[2]) {
    asm volatile(
        "mma.sync.aligned.m16n8k8.row.col.f32.tf32.tf32.f32 "
        "{%0,%1,%2,%3}, {%4,%5,%6,%7}, {%8,%9}, {%0,%1,%2,%3};"
        : "+f"(d[0]), "+f"(d[1]), "+f"(d[2]), "+f"(d[3])
        : "r"(a[0]), "r"(a[1]), "r"(a[2]), "r"(a[3]), "r"(b[0]), "r"(b[1]));
}

// ============================================================================
// Kernel 1/4: tf32 tensor-core GEMM  C[M,N] = A[M,K] @ B[K,N] (+ bias)
// (unchanged from R9 — measured 90us on QKV, tensor=31%)
// ============================================================================
#define GBK   16
#define GPAD  136

__global__ __launch_bounds__(256)
void mma_gemm_kernel(const float* __restrict__ A, const float* __restrict__ B,
                     float* __restrict__ C, int M, int N, int K,
                     const float* __restrict__ bias)
{
    __shared__ __align__(16) uint32_t As[GBK][GPAD];   // [k][m]
    __shared__ __align__(16) uint32_t Bs[GBK][GPAD];   // [k][n]

    int tid  = threadIdx.x;
    int warp = tid >> 5, lane = tid & 31;
    int g  = lane >> 2;
    int tg = lane & 3;
    int wm = (warp >> 2) * 64;
    int wn = (warp & 3) * 32;

    int brow = blockIdx.y * 128;
    int bcol = blockIdx.x * 128;

    const float* Ab = A + (size_t)brow * K;
    const float* Bb = B + bcol;

    float4 ra[2], rb[2];
    #pragma unroll
    for (int u = 0; u < 2; u++) {
        int ai = tid + u * 256;
        ra[u] = *(const float4*)(Ab + (size_t)(ai >> 2) * K + ((ai & 3) * 4));
        int bi = tid + u * 256;
        rb[u] = *(const float4*)(Bb + (size_t)(bi >> 5) * N + ((bi & 31) * 4));
    }

    float d[4][4][4];
    #pragma unroll
    for (int mi = 0; mi < 4; mi++)
        #pragma unroll
        for (int ni = 0; ni < 4; ni++)
            #pragma unroll
            for (int r = 0; r < 4; r++) d[mi][ni][r] = 0.f;

    for (int k0 = 0; k0 < K; k0 += GBK) {
        #pragma unroll
        for (int u = 0; u < 2; u++) {
            int ai = tid + u * 256;
            int ar = ai >> 2, ak = (ai & 3) * 4;
            As[ak + 0][ar] = f2tf32(ra[u].x);
            As[ak + 1][ar] = f2tf32(ra[u].y);
            As[ak + 2][ar] = f2tf32(ra[u].z);
            As[ak + 3][ar] = f2tf32(ra[u].w);
            int bi = tid + u * 256;
            int bk = bi >> 5, bn = (bi & 31) * 4;
            uint4 bw;
            bw.x = f2tf32(rb[u].x); bw.y = f2tf32(rb[u].y);
            bw.z = f2tf32(rb[u].z); bw.w = f2tf32(rb[u].w);
            *(uint4*)&Bs[bk][bn] = bw;
        }
        __syncthreads();

        if (k0 + GBK < K) {
            #pragma unroll
            for (int u = 0; u < 2; u++) {
                int ai = tid + u * 256;
                ra[u] = *(const float4*)(Ab + (size_t)(ai >> 2) * K
                                            + (k0 + GBK + (ai & 3) * 4));
                int bi = tid + u * 256;
                rb[u] = *(const float4*)(Bb + (size_t)(k0 + GBK + (bi >> 5)) * N
                                            + ((bi & 31) * 4));
            }
        }

        #pragma unroll
        for (int ks = 0; ks < 2; ks++) {
            int kb = ks * 8;
            uint32_t af[4][4], bf[4][2];
            #pragma unroll
            for (int mi = 0; mi < 4; mi++) {
                int m0 = wm + mi * 16;
                af[mi][0] = As[kb + tg    ][m0 + g    ];
                af[mi][1] = As[kb + tg    ][m0 + g + 8];
                af[mi][2] = As[kb + tg + 4][m0 + g    ];
                af[mi][3] = As[kb + tg + 4][m0 + g + 8];
            }
            #pragma unroll
            for (int ni = 0; ni < 4; ni++) {
                int n0 = wn + ni * 8;
                bf[ni][0] = Bs[kb + tg    ][n0 + g];
                bf[ni][1] = Bs[kb + tg + 4][n0 + g];
            }
            #pragma unroll
            for (int mi = 0; mi < 4; mi++)
                #pragma unroll
                for (int ni = 0; ni < 4; ni++)
                    mma_tf32(d[mi][ni], af[mi], bf[ni]);
        }
        __syncthreads();
    }

    #pragma unroll
    for (int mi = 0; mi < 4; mi++) {
        #pragma unroll
        for (int ni = 0; ni < 4; ni++) {
            int r0 = brow + wm + mi * 16 + g;
            int c  = bcol + wn + ni * 8 + 2 * tg;
            float2 v0, v1;
            v0.x = d[mi][ni][0]; v0.y = d[mi][ni][1];
            v1.x = d[mi][ni][2]; v1.y = d[mi][ni][3];
            if (bias) {
                float2 bb = *(const float2*)(bias + c);
                v0.x += bb.x; v0.y += bb.y;
                v1.x += bb.x; v1.y += bb.y;
            }
            *(float2*)(C + (size_t)r0 * N + c)       = v0;
            *(float2*)(C + (size_t)(r0 + 8) * N + c) = v1;
        }
    }
}

// ============================================================================
// Kernel 2: per-head LayerNorm + RoPE + scatter to [B,H,N,HD].  (unchanged)
// ============================================================================
__global__ __launch_bounds__(256)
void lnrope_kernel(const float* __restrict__ freq,
                   const float* __restrict__ qg, const float* __restrict__ qb,
                   const float* __restrict__ kg, const float* __restrict__ kb)
{
    int warp = (blockIdx.x * blockDim.x + threadIdx.x) >> 5;
    int lane = threadIdx.x & 31;
    const int TOTAL = BATCH * SEQ * HEADS;
    if (warp >= TOTAL) return;

    int h = warp & (HEADS - 1);
    int n = (warp >> 4) & (SEQ - 1);
    int b = warp >> 15;

    const float* src = g_qkv + (size_t)(b * SEQ + n) * QKVC + h * HDIM;
    int d0 = lane * 2;

    float2 q2 = *(const float2*)(src + d0);
    float2 k2 = *(const float2*)(src + DIMC + d0);
    float2 v2 = *(const float2*)(src + 2 * DIMC + d0);

    float sq  = q2.x + q2.y,           sk  = k2.x + k2.y;
    float sq2 = q2.x*q2.x + q2.y*q2.y, sk2 = k2.x*k2.x + k2.y*k2.y;
    #pragma unroll
    for (int off = 16; off; off >>= 1) {
        sq  += __shfl_xor_sync(0xffffffffu, sq,  off);
        sq2 += __shfl_xor_sync(0xffffffffu, sq2, off);
        sk  += __shfl_xor_sync(0xffffffffu, sk,  off);
        sk2 += __shfl_xor_sync(0xffffffffu, sk2, off);
    }
    float qm = sq * (1.f/64.f);
    float qv = sq2 * (1.f/64.f) - qm * qm;
    float qi = rsqrtf(qv + 1e-5f);
    float km = sk * (1.f/64.f);
    float kv = sk2 * (1.f/64.f) - km * km;
    float ki = rsqrtf(kv + 1e-5f);

    float qn0 = (q2.x - qm) * qi * qg[d0]     + qb[d0];
    float qn1 = (q2.y - qm) * qi * qg[d0 + 1] + qb[d0 + 1];
    float kn0 = (k2.x - km) * ki * kg[d0]     + kb[d0];
    float kn1 = (k2.y - km) * ki * kg[d0 + 1] + kb[d0 + 1];

    float co = freq[(n * 32 + lane) * 2 + 0];
    float si = freq[(n * 32 + lane) * 2 + 1];
    float qr = (qn0 * co - qn1 * si) * 0.125f;
    float qe = (qn0 * si + qn1 * co) * 0.125f;
    float kr =  kn0 * co - kn1 * si;
    float ke =  kn0 * si + kn1 * co;

    size_t o = ((size_t)(b * HEADS + h) * SEQ + n) * HDIM + d0;
    *(float2*)(g_q + o) = make_float2(qr, qe);
    *(float2*)(g_k + o) = make_float2(kr, ke);
    *(float2*)(g_v + o) = v2;
}

// ============================================================================
// Kernel 3: flash attention on tf32 tensor cores.
// Block = 128 Q-rows of one (b,h); 8 warps, each owns a 16-row strip x all
// 64 cols -> softmax is warp-local (quad shfl_xor 1,2). Q fragments live in
// registers for the whole block. K stored transposed Kt[d][key], V natural
// Vs[key][d] — both match the validated B[k][n] fragment indexing. P is kept
// in registers: C-frag -> A-frag layout conversion via quad shuffles.
// fp32 accumulate + fp32 online-softmax state throughout.
// ============================================================================
__global__ __launch_bounds__(256)
void attn_mma_kernel()
{
    __shared__ uint32_t Kt[HDIM][68];   // [d][key] tf32 (B for S = Q@K^T)
    __shared__ uint32_t Vs[64][68];     // [key][d] tf32 (B for O = P@V)

    int qt  = blockIdx.x;               // 0..15 (128-row q tiles)
    int bh  = blockIdx.y;               // 0..31 (b*16 + h)
    int tid = threadIdx.x;
    int warp = tid >> 5, lane = tid & 31;
    int g = lane >> 2, tg = lane & 3;

    const float* Qb = g_q + ((size_t)bh * SEQ + qt * 128 + warp * 16) * HDIM;
    const float* Kb = g_k + (size_t)bh * SEQ * HDIM;
    const float* Vb = g_v + (size_t)bh * SEQ * HDIM;

    // Q fragments in registers: qf[ki] = A-frag for k-chunk ki (cols ki*8..+7)
    uint32_t qf[8][4];
    #pragma unroll
    for (int ki = 0; ki < 8; ki++) {
        qf[ki][0] = f2tf32(Qb[(g    ) * HDIM + ki * 8 + tg    ]);
        qf[ki][1] = f2tf32(Qb[(g + 8) * HDIM + ki * 8 + tg    ]);
        qf[ki][2] = f2tf32(Qb[(g    ) * HDIM + ki * 8 + tg + 4]);
        qf[ki][3] = f2tf32(Qb[(g + 8) * HDIM + ki * 8 + tg + 4]);
    }

    float oc[8][4];
    #pragma unroll
    for (int ni = 0; ni < 8; ni++)
        #pragma unroll
        for (int r = 0; r < 4; r++) oc[ni][r] = 0.f;
    float m0 = -INFINITY, m1 = -INFINITY, l0 = 0.f, l1 = 0.f;

    for (int kt = 0; kt < SEQ / 64; kt++) {
        // ---- load K (transposed) and V (natural) tiles, tf32-converted ----
        #pragma unroll
        for (int i = tid; i < 64 * 16; i += 256) {
            int r  = i >> 4;             // key 0..63
            int d4 = (i & 15) * 4;
            float4 kv = *(const float4*)(Kb + (size_t)(kt * 64 + r) * HDIM + d4);
            Kt[d4 + 0][r] = f2tf32(kv.x);
            Kt[d4 + 1][r] = f2tf32(kv.y);
            Kt[d4 + 2][r] = f2tf32(kv.z);
            Kt[d4 + 3][r] = f2tf32(kv.w);
            float4 vv = *(const float4*)(Vb + (size_t)(kt * 64 + r) * HDIM + d4);
            uint4 vw;
            vw.x = f2tf32(vv.x); vw.y = f2tf32(vv.y);
            vw.z = f2tf32(vv.z); vw.w = f2tf32(vv.w);
            *(uint4*)&Vs[r][d4] = vw;
        }
        __syncthreads();

        // ---- S = Q @ K^T (q pre-scaled by 1/8); sc[ni] covers keys ni*8..+7
        float sc[8][4];
        #pragma unroll
        for (int ni = 0; ni < 8; ni++)
            #pragma unroll
            for (int r = 0; r < 4; r++) sc[ni][r] = 0.f;
        #pragma unroll
        for (int ki = 0; ki < 8; ki++) {
            #pragma unroll
            for (int ni = 0; ni < 8; ni++) {
                uint32_t b[2];
                b[0] = Kt[ki * 8 + tg    ][ni * 8 + g];
                b[1] = Kt[ki * 8 + tg + 4][ni * 8 + g];
                mma_tf32(sc[ni], qf[ki], b);
            }
        }

        // ---- online softmax (rows g and g+8; quad-local reductions) ----
        float mx0 = -INFINITY, mx1 = -INFINITY;
        #pragma unroll
        for (int ni = 0; ni < 8; ni++) {
            mx0 = fmaxf(mx0, fmaxf(sc[ni][0], sc[ni][1]));
            mx1 = fmaxf(mx1, fmaxf(sc[ni][2], sc[ni][3]));
        }
        mx0 = fmaxf(mx0, __shfl_xor_sync(0xffffffffu, mx0, 1));
        mx0 = fmaxf(mx0, __shfl_xor_sync(0xffffffffu, mx0, 2));
        mx1 = fmaxf(mx1, __shfl_xor_sync(0xffffffffu, mx1, 1));
        mx1 = fmaxf(mx1, __shfl_xor_sync(0xffffffffu, mx1, 2));

        float mn0 = fmaxf(m0, mx0), mn1 = fmaxf(m1, mx1);
        float a0 = __expf(m0 - mn0), a1 = __expf(m1 - mn1);

        uint32_t pu[8][4];
        float s0 = 0.f, s1 = 0.f;
        #pragma unroll
        for (int ni = 0; ni < 8; ni++) {
            float p0 = __expf(sc[ni][0] - mn0);
            float p1 = __expf(sc[ni][1] - mn0);
            float p2 = __expf(sc[ni][2] - mn1);
            float p3 = __expf(sc[ni][3] - mn1);
            s0 += p0 + p1; s1 += p2 + p3;
            pu[ni][0] = f2tf32(p0); pu[ni][1] = f2tf32(p1);
            pu[ni][2] = f2tf32(p2); pu[ni][3] = f2tf32(p3);
        }
        s0 += __shfl_xor_sync(0xffffffffu, s0, 1);
        s0 += __shfl_xor_sync(0xffffffffu, s0, 2);
        s1 += __shfl_xor_sync(0xffffffffu, s1, 1);
        s1 += __shfl_xor_sync(0xffffffffu, s1, 2);

        l0 = a0 * l0 + s0;  l1 = a1 * l1 + s1;
        m0 = mn0;           m1 = mn1;
        #pragma unroll
        for (int ni = 0; ni < 8; ni++) {
            oc[ni][0] *= a0; oc[ni][1] *= a0;
            oc[ni][2] *= a1; oc[ni][3] *= a1;
        }

        // ---- O += P @ V; P C-frags -> A-frags via quad shuffles ----
        int base = lane & ~3;
        int h0 = base | (tg >> 1);      // source lane for chunk-col tg
        bool odd = (tg & 1);
        #pragma unroll
        for (int ki = 0; ki < 8; ki++) {
            uint32_t a[4], t0, t1;
            t0 = __shfl_sync(0xffffffffu, pu[ki][0], h0);
            t1 = __shfl_sync(0xffffffffu, pu[ki][1], h0);
            a[0] = odd ? t1 : t0;                         // P[g][tg]
            t0 = __shfl_sync(0xffffffffu, pu[ki][2], h0);
            t1 = __shfl_sync(0xffffffffu, pu[ki][3], h0);
            a[1] = odd ? t1 : t0;                         // P[g+8][tg]
            t0 = __shfl_sync(0xffffffffu, pu[ki][0], h0 + 2);
            t1 = __shfl_sync(0xffffffffu, pu[ki][1], h0 + 2);
            a[2] = odd ? t1 : t0;                         // P[g][tg+4]
            t0 = __shfl_sync(0xffffffffu, pu[ki][2], h0 + 2);
            t1 = __shfl_sync(0xffffffffu, pu[ki][3], h0 + 2);
            a[3] = odd ? t1 : t0;                         // P[g+8][tg+4]
            #pragma unroll
            for (int ni = 0; ni < 8; ni++) {
                uint32_t b[2];
                b[0] = Vs[ki * 8 + tg    ][ni * 8 + g];
                b[1] = Vs[ki * 8 + tg + 4][ni * 8 + g];
                mma_tf32(oc[ni], a, b);
            }
        }
        __syncthreads();   // all reads of Kt/Vs done before next tile load
    }

    // ---- epilogue: normalize, write [B, N, DIM] ----
    int b = bh >> 4, h = bh & 15;
    int row0 = qt * 128 + warp * 16 + g;
    float i0 = 1.f / l0, i1 = 1.f / l1;
    #pragma unroll
    for (int ni = 0; ni < 8; ni++) {
        int d = h * HDIM + ni * 8 + 2 * tg;
        float2 v;
        v.x = oc[ni][0] * i0; v.y = oc[ni][1] * i0;
        *(float2*)(g_attn + (size_t)(b * SEQ + row0) * DIMC + d) = v;
        v.x = oc[ni][2] * i1; v.y = oc[ni][3] * i1;
        *(float2*)(g_attn + (size_t)(b * SEQ + row0 + 8) * DIMC + d) = v;
    }
}

// ============================================================================
// launch
// ============================================================================
extern "C" void kernel_launch(void* const* d_in, const int* in_sizes, int n_in,
                              void* d_out, int out_size)
{
    const float* x    = (const float*)d_in[0];
    const float* freq = (const float*)d_in[1];
    const float* Wqkv = (const float*)d_in[2];
    const float* qg   = (const float*)d_in[3];
    const float* qb   = (const float*)d_in[4];
    const float* kg   = (const float*)d_in[5];
    const float* kb   = (const float*)d_in[6];
    const float* Wp   = (const float*)d_in[7];
    const float* bp   = (const float*)d_in[8];
    float* out = (float*)d_out;

    float *qkv_p = nullptr, *attn_p = nullptr;
    cudaGetSymbolAddress((void**)&qkv_p,  g_qkv);
    cudaGetSymbolAddress((void**)&attn_p, g_attn);

    // 1. qkv = x @ Wqkv          [4096,1024] @ [1024,3072]  (tf32 mma)
    {
        dim3 grid(QKVC / 128, ROWS / 128);
        mma_gemm_kernel<<<grid, 256>>>(x, Wqkv, qkv_p, ROWS, QKVC, DIMC, nullptr);
    }
    // 2. LN + RoPE + scatter to [B,H,N,HD] (Q pre-scaled by 1/8)
    {
        int warps = BATCH * SEQ * HEADS;
        lnrope_kernel<<<warps / 8, 256>>>(freq, qg, qb, kg, kb);
    }
    // 3. flash attention (tf32 mma) -> g_attn [B,N,DIM]
    {
        dim3 grid(SEQ / 128, BATCH * HEADS);
        attn_mma_kernel<<<grid, 256>>>();
    }
    // 4. out = attn @ Wproj + bproj   [4096,1024] @ [1024,1024]  (tf32 mma)
    {
        dim3 grid(DIMC / 128, ROWS / 128);
        mma_gemm_kernel<<<grid, 256>>>(attn_p, Wp, out, ROWS, DIMC, DIMC, bp);
    }
}

// round 14
// speedup vs baseline: 2.4477x; 1.0643x over previous
// build-id: r14-occ2-attnprefetch
#include <cuda_runtime.h>
#include <math.h>
#include <stdint.h>

// Problem constants
#define DIMC   1024
#define HEADS  16
#define HDIM   64
#define BATCH  2
#define SEQ    2048
#define ROWS   (BATCH*SEQ)          // 4096
#define QKVC   (3*DIMC)             // 3072

// ---------------- scratch (static device memory; no cudaMalloc allowed) ----
__device__ float g_qkv [ROWS * QKVC];            // x @ Wqkv
__device__ float g_q   [BATCH*HEADS*SEQ*HDIM];   // [B,H,N,HD] rope'd+scaled
__device__ float g_k   [BATCH*HEADS*SEQ*HDIM];
__device__ float g_v   [BATCH*HEADS*SEQ*HDIM];
__device__ float g_attn[ROWS * DIMC];            // attention out [B,N,DIM]

// ============================================================================
// tf32 mma helpers (fragment mapping validated R9/R13)
// ============================================================================
__device__ __forceinline__ uint32_t f2tf32(float x) {
    uint32_t r;
    asm("cvt.rna.tf32.f32 %0, %1;" : "=r"(r) : "f"(x));
    return r;
}

__device__ __forceinline__ void mma_tf32(float d[4], const uint32_t a[4],
                                         const uint32_t b[2]) {
    asm volatile(
        "mma.sync.aligned.m16n8k8.row.col.f32.tf32.tf32.f32 "
        "{%0,%1,%2,%3}, {%4,%5,%6,%7}, {%8,%9}, {%0,%1,%2,%3};"
        : "+f"(d[0]), "+f"(d[1]), "+f"(d[2]), "+f"(d[3])
        : "r"(a[0]), "r"(a[1]), "r"(a[2]), "r"(a[3]), "r"(b[0]), "r"(b[1]));
}

// ============================================================================
// Kernel 1/4: tf32 tensor-core GEMM  C[M,N] = A[M,K] @ B[K,N] (+ bias)
// R9 kernel + __launch_bounds__(256, 2): force 2 CTAs/SM (regs 121<=128,
// smem 2x17.4KB fits) to double latency hiding; no numeric change.
// ============================================================================
#define GBK   16
#define GPAD  136

__global__ __launch_bounds__(256, 2)
void mma_gemm_kernel(const float* __restrict__ A, const float* __restrict__ B,
                     float* __restrict__ C, int M, int N, int K,
                     const float* __restrict__ bias)
{
    __shared__ __align__(16) uint32_t As[GBK][GPAD];   // [k][m]
    __shared__ __align__(16) uint32_t Bs[GBK][GPAD];   // [k][n]

    int tid  = threadIdx.x;
    int warp = tid >> 5, lane = tid & 31;
    int g  = lane >> 2;
    int tg = lane & 3;
    int wm = (warp >> 2) * 64;
    int wn = (warp & 3) * 32;

    int brow = blockIdx.y * 128;
    int bcol = blockIdx.x * 128;

    const float* Ab = A + (size_t)brow * K;
    const float* Bb = B + bcol;

    float4 ra[2], rb[2];
    #pragma unroll
    for (int u = 0; u < 2; u++) {
        int ai = tid + u * 256;
        ra[u] = *(const float4*)(Ab + (size_t)(ai >> 2) * K + ((ai & 3) * 4));
        int bi = tid + u * 256;
        rb[u] = *(const float4*)(Bb + (size_t)(bi >> 5) * N + ((bi & 31) * 4));
    }

    float d[4][4][4];
    #pragma unroll
    for (int mi = 0; mi < 4; mi++)
        #pragma unroll
        for (int ni = 0; ni < 4; ni++)
            #pragma unroll
            for (int r = 0; r < 4; r++) d[mi][ni][r] = 0.f;

    for (int k0 = 0; k0 < K; k0 += GBK) {
        #pragma unroll
        for (int u = 0; u < 2; u++) {
            int ai = tid + u * 256;
            int ar = ai >> 2, ak = (ai & 3) * 4;
            As[ak + 0][ar] = f2tf32(ra[u].x);
            As[ak + 1][ar] = f2tf32(ra[u].y);
            As[ak + 2][ar] = f2tf32(ra[u].z);
            As[ak + 3][ar] = f2tf32(ra[u].w);
            int bi = tid + u * 256;
            int bk = bi >> 5, bn = (bi & 31) * 4;
            uint4 bw;
            bw.x = f2tf32(rb[u].x); bw.y = f2tf32(rb[u].y);
            bw.z = f2tf32(rb[u].z); bw.w = f2tf32(rb[u].w);
            *(uint4*)&Bs[bk][bn] = bw;
        }
        __syncthreads();

        if (k0 + GBK < K) {
            #pragma unroll
            for (int u = 0; u < 2; u++) {
                int ai = tid + u * 256;
                ra[u] = *(const float4*)(Ab + (size_t)(ai >> 2) * K
                                            + (k0 + GBK + (ai & 3) * 4));
                int bi = tid + u * 256;
                rb[u] = *(const float4*)(Bb + (size_t)(k0 + GBK + (bi >> 5)) * N
                                            + ((bi & 31) * 4));
            }
        }

        #pragma unroll
        for (int ks = 0; ks < 2; ks++) {
            int kb = ks * 8;
            uint32_t af[4][4], bf[4][2];
            #pragma unroll
            for (int mi = 0; mi < 4; mi++) {
                int m0 = wm + mi * 16;
                af[mi][0] = As[kb + tg    ][m0 + g    ];
                af[mi][1] = As[kb + tg    ][m0 + g + 8];
                af[mi][2] = As[kb + tg + 4][m0 + g    ];
                af[mi][3] = As[kb + tg + 4][m0 + g + 8];
            }
            #pragma unroll
            for (int ni = 0; ni < 4; ni++) {
                int n0 = wn + ni * 8;
                bf[ni][0] = Bs[kb + tg    ][n0 + g];
                bf[ni][1] = Bs[kb + tg + 4][n0 + g];
            }
            #pragma unroll
            for (int mi = 0; mi < 4; mi++)
                #pragma unroll
                for (int ni = 0; ni < 4; ni++)
                    mma_tf32(d[mi][ni], af[mi], bf[ni]);
        }
        __syncthreads();
    }

    #pragma unroll
    for (int mi = 0; mi < 4; mi++) {
        #pragma unroll
        for (int ni = 0; ni < 4; ni++) {
            int r0 = brow + wm + mi * 16 + g;
            int c  = bcol + wn + ni * 8 + 2 * tg;
            float2 v0, v1;
            v0.x = d[mi][ni][0]; v0.y = d[mi][ni][1];
            v1.x = d[mi][ni][2]; v1.y = d[mi][ni][3];
            if (bias) {
                float2 bb = *(const float2*)(bias + c);
                v0.x += bb.x; v0.y += bb.y;
                v1.x += bb.x; v1.y += bb.y;
            }
            *(float2*)(C + (size_t)r0 * N + c)       = v0;
            *(float2*)(C + (size_t)(r0 + 8) * N + c) = v1;
        }
    }
}

// ============================================================================
// Kernel 2: per-head LayerNorm + RoPE + scatter to [B,H,N,HD].  (unchanged)
// ============================================================================
__global__ __launch_bounds__(256)
void lnrope_kernel(const float* __restrict__ freq,
                   const float* __restrict__ qg, const float* __restrict__ qb,
                   const float* __restrict__ kg, const float* __restrict__ kb)
{
    int warp = (blockIdx.x * blockDim.x + threadIdx.x) >> 5;
    int lane = threadIdx.x & 31;
    const int TOTAL = BATCH * SEQ * HEADS;
    if (warp >= TOTAL) return;

    int h = warp & (HEADS - 1);
    int n = (warp >> 4) & (SEQ - 1);
    int b = warp >> 15;

    const float* src = g_qkv + (size_t)(b * SEQ + n) * QKVC + h * HDIM;
    int d0 = lane * 2;

    float2 q2 = *(const float2*)(src + d0);
    float2 k2 = *(const float2*)(src + DIMC + d0);
    float2 v2 = *(const float2*)(src + 2 * DIMC + d0);

    float sq  = q2.x + q2.y,           sk  = k2.x + k2.y;
    float sq2 = q2.x*q2.x + q2.y*q2.y, sk2 = k2.x*k2.x + k2.y*k2.y;
    #pragma unroll
    for (int off = 16; off; off >>= 1) {
        sq  += __shfl_xor_sync(0xffffffffu, sq,  off);
        sq2 += __shfl_xor_sync(0xffffffffu, sq2, off);
        sk  += __shfl_xor_sync(0xffffffffu, sk,  off);
        sk2 += __shfl_xor_sync(0xffffffffu, sk2, off);
    }
    float qm = sq * (1.f/64.f);
    float qv = sq2 * (1.f/64.f) - qm * qm;
    float qi = rsqrtf(qv + 1e-5f);
    float km = sk * (1.f/64.f);
    float kv = sk2 * (1.f/64.f) - km * km;
    float ki = rsqrtf(kv + 1e-5f);

    float qn0 = (q2.x - qm) * qi * qg[d0]     + qb[d0];
    float qn1 = (q2.y - qm) * qi * qg[d0 + 1] + qb[d0 + 1];
    float kn0 = (k2.x - km) * ki * kg[d0]     + kb[d0];
    float kn1 = (k2.y - km) * ki * kg[d0 + 1] + kb[d0 + 1];

    float co = freq[(n * 32 + lane) * 2 + 0];
    float si = freq[(n * 32 + lane) * 2 + 1];
    float qr = (qn0 * co - qn1 * si) * 0.125f;
    float qe = (qn0 * si + qn1 * co) * 0.125f;
    float kr =  kn0 * co - kn1 * si;
    float ke =  kn0 * si + kn1 * co;

    size_t o = ((size_t)(b * HEADS + h) * SEQ + n) * HDIM + d0;
    *(float2*)(g_q + o) = make_float2(qr, qe);
    *(float2*)(g_k + o) = make_float2(kr, ke);
    *(float2*)(g_v + o) = v2;
}

// ============================================================================
// Kernel 3: flash attention on tf32 tensor cores (R13 kernel + register
// prefetch of the next K/V tile so L2 latency overlaps compute).
// ============================================================================
__global__ __launch_bounds__(256)
void attn_mma_kernel()
{
    __shared__ uint32_t Kt[HDIM][68];   // [d][key] tf32 (B for S = Q@K^T)
    __shared__ uint32_t Vs[64][68];     // [key][d] tf32 (B for O = P@V)

    int qt  = blockIdx.x;               // 0..15 (128-row q tiles)
    int bh  = blockIdx.y;               // 0..31 (b*16 + h)
    int tid = threadIdx.x;
    int warp = tid >> 5, lane = tid & 31;
    int g = lane >> 2, tg = lane & 3;

    const float* Qb = g_q + ((size_t)bh * SEQ + qt * 128 + warp * 16) * HDIM;
    const float* Kb = g_k + (size_t)bh * SEQ * HDIM;
    const float* Vb = g_v + (size_t)bh * SEQ * HDIM;

    // Q fragments in registers: qf[ki] = A-frag for k-chunk ki
    uint32_t qf[8][4];
    #pragma unroll
    for (int ki = 0; ki < 8; ki++) {
        qf[ki][0] = f2tf32(Qb[(g    ) * HDIM + ki * 8 + tg    ]);
        qf[ki][1] = f2tf32(Qb[(g + 8) * HDIM + ki * 8 + tg    ]);
        qf[ki][2] = f2tf32(Qb[(g    ) * HDIM + ki * 8 + tg + 4]);
        qf[ki][3] = f2tf32(Qb[(g + 8) * HDIM + ki * 8 + tg + 4]);
    }

    float oc[8][4];
    #pragma unroll
    for (int ni = 0; ni < 8; ni++)
        #pragma unroll
        for (int r = 0; r < 4; r++) oc[ni][r] = 0.f;
    float m0 = -INFINITY, m1 = -INFINITY, l0 = 0.f, l1 = 0.f;

    // prologue: tile 0 into registers (each thread owns 4 (r,d4) slots)
    float4 pk[4], pv[4];
    #pragma unroll
    for (int u = 0; u < 4; u++) {
        int i  = tid + u * 256;
        int r  = i >> 4;
        int d4 = (i & 15) * 4;
        pk[u] = *(const float4*)(Kb + (size_t)r * HDIM + d4);
        pv[u] = *(const float4*)(Vb + (size_t)r * HDIM + d4);
    }

    for (int kt = 0; kt < SEQ / 64; kt++) {
        // ---- stage prefetched regs -> smem (tf32 convert) ----
        #pragma unroll
        for (int u = 0; u < 4; u++) {
            int i  = tid + u * 256;
            int r  = i >> 4;
            int d4 = (i & 15) * 4;
            Kt[d4 + 0][r] = f2tf32(pk[u].x);
            Kt[d4 + 1][r] = f2tf32(pk[u].y);
            Kt[d4 + 2][r] = f2tf32(pk[u].z);
            Kt[d4 + 3][r] = f2tf32(pk[u].w);
            uint4 vw;
            vw.x = f2tf32(pv[u].x); vw.y = f2tf32(pv[u].y);
            vw.z = f2tf32(pv[u].z); vw.w = f2tf32(pv[u].w);
            *(uint4*)&Vs[r][d4] = vw;
        }
        __syncthreads();   // publish tile kt

        // ---- prefetch tile kt+1 (overlaps with all compute below) ----
        if (kt + 1 < SEQ / 64) {
            #pragma unroll
            for (int u = 0; u < 4; u++) {
                int i  = tid + u * 256;
                int r  = (kt + 1) * 64 + (i >> 4);
                int d4 = (i & 15) * 4;
                pk[u] = *(const float4*)(Kb + (size_t)r * HDIM + d4);
                pv[u] = *(const float4*)(Vb + (size_t)r * HDIM + d4);
            }
        }

        // ---- S = Q @ K^T (q pre-scaled by 1/8) ----
        float sc[8][4];
        #pragma unroll
        for (int ni = 0; ni < 8; ni++)
            #pragma unroll
            for (int r = 0; r < 4; r++) sc[ni][r] = 0.f;
        #pragma unroll
        for (int ki = 0; ki < 8; ki++) {
            #pragma unroll
            for (int ni = 0; ni < 8; ni++) {
                uint32_t b[2];
                b[0] = Kt[ki * 8 + tg    ][ni * 8 + g];
                b[1] = Kt[ki * 8 + tg + 4][ni * 8 + g];
                mma_tf32(sc[ni], qf[ki], b);
            }
        }

        // ---- online softmax (rows g and g+8; quad-local reductions) ----
        float mx0 = -INFINITY, mx1 = -INFINITY;
        #pragma unroll
        for (int ni = 0; ni < 8; ni++) {
            mx0 = fmaxf(mx0, fmaxf(sc[ni][0], sc[ni][1]));
            mx1 = fmaxf(mx1, fmaxf(sc[ni][2], sc[ni][3]));
        }
        mx0 = fmaxf(mx0, __shfl_xor_sync(0xffffffffu, mx0, 1));
        mx0 = fmaxf(mx0, __shfl_xor_sync(0xffffffffu, mx0, 2));
        mx1 = fmaxf(mx1, __shfl_xor_sync(0xffffffffu, mx1, 1));
        mx1 = fmaxf(mx1, __shfl_xor_sync(0xffffffffu, mx1, 2));

        float mn0 = fmaxf(m0, mx0), mn1 = fmaxf(m1, mx1);
        float a0 = __expf(m0 - mn0), a1 = __expf(m1 - mn1);

        uint32_t pu[8][4];
        float s0 = 0.f, s1 = 0.f;
        #pragma unroll
        for (int ni = 0; ni < 8; ni++) {
            float p0 = __expf(sc[ni][0] - mn0);
            float p1 = __expf(sc[ni][1] - mn0);
            float p2 = __expf(sc[ni][2] - mn1);
            float p3 = __expf(sc[ni][3] - mn1);
            s0 += p0 + p1; s1 += p2 + p3;
            pu[ni][0] = f2tf32(p0); pu[ni][1] = f2tf32(p1);
            pu[ni][2] = f2tf32(p2); pu[ni][3] = f2tf32(p3);
        }
        s0 += __shfl_xor_sync(0xffffffffu, s0, 1);
        s0 += __shfl_xor_sync(0xffffffffu, s0, 2);
        s1 += __shfl_xor_sync(0xffffffffu, s1, 1);
        s1 += __shfl_xor_sync(0xffffffffu, s1, 2);

        l0 = a0 * l0 + s0;  l1 = a1 * l1 + s1;
        m0 = mn0;           m1 = mn1;
        #pragma unroll
        for (int ni = 0; ni < 8; ni++) {
            oc[ni][0] *= a0; oc[ni][1] *= a0;
            oc[ni][2] *= a1; oc[ni][3] *= a1;
        }

        // ---- O += P @ V; P C-frags -> A-frags via quad shuffles ----
        int base = lane & ~3;
        int h0 = base | (tg >> 1);
        bool odd = (tg & 1);
        #pragma unroll
        for (int ki = 0; ki < 8; ki++) {
            uint32_t a[4], t0, t1;
            t0 = __shfl_sync(0xffffffffu, pu[ki][0], h0);
            t1 = __shfl_sync(0xffffffffu, pu[ki][1], h0);
            a[0] = odd ? t1 : t0;                         // P[g][tg]
            t0 = __shfl_sync(0xffffffffu, pu[ki][2], h0);
            t1 = __shfl_sync(0xffffffffu, pu[ki][3], h0);
            a[1] = odd ? t1 : t0;                         // P[g+8][tg]
            t0 = __shfl_sync(0xffffffffu, pu[ki][0], h0 + 2);
            t1 = __shfl_sync(0xffffffffu, pu[ki][1], h0 + 2);
            a[2] = odd ? t1 : t0;                         // P[g][tg+4]
            t0 = __shfl_sync(0xffffffffu, pu[ki][2], h0 + 2);
            t1 = __shfl_sync(0xffffffffu, pu[ki][3], h0 + 2);
            a[3] = odd ? t1 : t0;                         // P[g+8][tg+4]
            #pragma unroll
            for (int ni = 0; ni < 8; ni++) {
                uint32_t b[2];
                b[0] = Vs[ki * 8 + tg    ][ni * 8 + g];
                b[1] = Vs[ki * 8 + tg + 4][ni * 8 + g];
                mma_tf32(oc[ni], a, b);
            }
        }
        __syncthreads();   // all reads of Kt/Vs done before next store phase
    }

    // ---- epilogue: normalize, write [B, N, DIM] ----
    int b = bh >> 4, h = bh & 15;
    int row0 = qt * 128 + warp * 16 + g;
    float i0 = 1.f / l0, i1 = 1.f / l1;
    #pragma unroll
    for (int ni = 0; ni < 8; ni++) {
        int d = h * HDIM + ni * 8 + 2 * tg;
        float2 v;
        v.x = oc[ni][0] * i0; v.y = oc[ni][1] * i0;
        *(float2*)(g_attn + (size_t)(b * SEQ + row0) * DIMC + d) = v;
        v.x = oc[ni][2] * i1; v.y = oc[ni][3] * i1;
        *(float2*)(g_attn + (size_t)(b * SEQ + row0 + 8) * DIMC + d) = v;
    }
}

// ============================================================================
// launch
// ============================================================================
extern "C" void kernel_launch(void* const* d_in, const int* in_sizes, int n_in,
                              void* d_out, int out_size)
{
    const float* x    = (const float*)d_in[0];
    const float* freq = (const float*)d_in[1];
    const float* Wqkv = (const float*)d_in[2];
    const float* qg   = (const float*)d_in[3];
    const float* qb   = (const float*)d_in[4];
    const float* kg   = (const float*)d_in[5];
    const float* kb   = (const float*)d_in[6];
    const float* Wp   = (const float*)d_in[7];
    const float* bp   = (const float*)d_in[8];
    float* out = (float*)d_out;

    float *qkv_p = nullptr, *attn_p = nullptr;
    cudaGetSymbolAddress((void**)&qkv_p,  g_qkv);
    cudaGetSymbolAddress((void**)&attn_p, g_attn);

    // 1. qkv = x @ Wqkv          [4096,1024] @ [1024,3072]  (tf32 mma)
    {
        dim3 grid(QKVC / 128, ROWS / 128);
        mma_gemm_kernel<<<grid, 256>>>(x, Wqkv, qkv_p, ROWS, QKVC, DIMC, nullptr);
    }
    // 2. LN + RoPE + scatter to [B,H,N,HD] (Q pre-scaled by 1/8)
    {
        int warps = BATCH * SEQ * HEADS;
        lnrope_kernel<<<warps / 8, 256>>>(freq, qg, qb, kg, kb);
    }
    // 3. flash attention (tf32 mma) -> g_attn [B,N,DIM]
    {
        dim3 grid(SEQ / 128, BATCH * HEADS);
        attn_mma_kernel<<<grid, 256>>>();
    }
    // 4. out = attn @ Wproj + bproj   [4096,1024] @ [1024,1024]  (tf32 mma)
    {
        dim3 grid(DIMC / 128, ROWS / 128);
        mma_gemm_kernel<<<grid, 256>>>(attn_p, Wp, out, ROWS, DIMC, DIMC, bp);
    }
}

// round 16
// speedup vs baseline: 3.5718x; 1.4592x over previous
// build-id: r15-fp16-mma
#include <cuda_runtime.h>
#include <cuda_fp16.h>
#include <math.h>
#include <stdint.h>
#include <string.h>

// Problem constants
#define DIMC   1024
#define HEADS  16
#define HDIM   64
#define BATCH  2
#define SEQ    2048
#define ROWS   (BATCH*SEQ)          // 4096
#define QKVC   (3*DIMC)             // 3072

// ---------------- scratch (static device memory; no cudaMalloc allowed) ----
__device__ float g_qkv [ROWS * QKVC];            // x @ Wqkv
__device__ float g_q   [BATCH*HEADS*SEQ*HDIM];   // [B,H,N,HD] rope'd+scaled
__device__ float g_k   [BATCH*HEADS*SEQ*HDIM];
__device__ float g_v   [BATCH*HEADS*SEQ*HDIM];
__device__ float g_attn[ROWS * DIMC];            // attention out [B,N,DIM]

// ============================================================================
// fp16 mma helpers. m16n8k16, row.col, fp32 accumulate.
// A-frag (4 regs, half2): a0=A[g][2tg,2tg+1] a1=A[g+8][same] a2=A[g][2tg+8,+9]
//   a3=A[g+8][2tg+8,+9].  B-frag (2 regs): b0={B[2tg][n=g],B[2tg+1][g]}
//   b1={B[2tg+8][g],B[2tg+9][g]}.  C-frag: c0=[g][2tg] c1=[g][2tg+1]
//   c2=[g+8][2tg] c3=[g+8][2tg+1]   (same C layout as the validated tf32 path)
// ============================================================================
__device__ __forceinline__ uint32_t packh2(float lo, float hi) {
    __half2 h = __float22half2_rn(make_float2(lo, hi));  // .x -> low 16 bits
    uint32_t u;
    memcpy(&u, &h, 4);
    return u;
}

__device__ __forceinline__ void mma_f16(float d[4], const uint32_t a[4],
                                        const uint32_t b[2]) {
    asm volatile(
        "mma.sync.aligned.m16n8k16.row.col.f32.f16.f16.f32 "
        "{%0,%1,%2,%3}, {%4,%5,%6,%7}, {%8,%9}, {%0,%1,%2,%3};"
        : "+f"(d[0]), "+f"(d[1]), "+f"(d[2]), "+f"(d[3])
        : "r"(a[0]), "r"(a[1]), "r"(a[2]), "r"(a[3]), "r"(b[0]), "r"(b[1]));
}

// ============================================================================
// Kernel 1/4: fp16 tensor-core GEMM  C[M,N] = A[M,K] @ B[K,N] (+ bias)
// Block 128x128x16, 8 warps (2m x 4n), warp tile 64x32, ONE k16 mma step
// per tile. smem holds half2 pairs along k: As_h2[m][k2], Bs_h2[n][k2],
// row stride 10 (uint32) -> fragment LDS conflict-free (10g+tg distinct).
// Double-buffered: one __syncthreads per k-tile.
// ============================================================================
#define GBK   16
#define GS    10     // h2 row stride (8 pairs + pad 2; even for uint2 stores)

__global__ __launch_bounds__(256, 2)
void mma_gemm_kernel(const float* __restrict__ A, const float* __restrict__ B,
                     float* __restrict__ C, int M, int N, int K,
                     const float* __restrict__ bias)
{
    __shared__ __align__(16) uint32_t As[2][128 * GS];
    __shared__ __align__(16) uint32_t Bs[2][128 * GS];

    int tid  = threadIdx.x;
    int warp = tid >> 5, lane = tid & 31;
    int g  = lane >> 2;
    int tg = lane & 3;
    int wm = (warp >> 2) * 64;
    int wn = (warp & 3) * 32;

    int brow = blockIdx.y * 128;
    int bcol = blockIdx.x * 128;

    const float* Ab = A + (size_t)brow * K;
    const float* Bb = B + bcol;

    // A: 2 float4/thread: ai=tid+256u -> m=ai>>2, kc=ai&3 (k=4kc..4kc+3)
    // B: 1 slot/thread: n4=(lane-ish), kp=k-pair row; loads two k-rows
    int am[2], akc[2];
    #pragma unroll
    for (int u = 0; u < 2; u++) { int ai = tid + u * 256; am[u] = ai >> 2; akc[u] = ai & 3; }
    int bn4 = (tid & 31) * 4;
    int bkp = tid >> 5;               // 0..7 -> k = 2*bkp, 2*bkp+1

    float4 ra[2];
    float  rb0[4], rb1[4];

    #pragma unroll
    for (int u = 0; u < 2; u++)
        ra[u] = *(const float4*)(Ab + (size_t)am[u] * K + 4 * akc[u]);
    *(float4*)rb0 = *(const float4*)(Bb + (size_t)(2 * bkp    ) * N + bn4);
    *(float4*)rb1 = *(const float4*)(Bb + (size_t)(2 * bkp + 1) * N + bn4);

    // store tile0 -> buf0
    #pragma unroll
    for (int u = 0; u < 2; u++) {
        uint2 w;
        w.x = packh2(ra[u].x, ra[u].y);
        w.y = packh2(ra[u].z, ra[u].w);
        *(uint2*)&As[0][am[u] * GS + 2 * akc[u]] = w;
    }
    #pragma unroll
    for (int j = 0; j < 4; j++)
        Bs[0][(bn4 + j) * GS + bkp] = packh2(rb0[j], rb1[j]);
    __syncthreads();

    float d[4][4][4];
    #pragma unroll
    for (int mi = 0; mi < 4; mi++)
        #pragma unroll
        for (int ni = 0; ni < 4; ni++)
            #pragma unroll
            for (int r = 0; r < 4; r++) d[mi][ni][r] = 0.f;

    int p = 0;
    const int NT = K / GBK;
    for (int t = 0; t < NT; t++) {
        int k0n = (t + 1) * GBK;
        if (t + 1 < NT) {             // issue next-tile loads early
            #pragma unroll
            for (int u = 0; u < 2; u++)
                ra[u] = *(const float4*)(Ab + (size_t)am[u] * K + k0n + 4 * akc[u]);
            *(float4*)rb0 = *(const float4*)(Bb + (size_t)(k0n + 2 * bkp    ) * N + bn4);
            *(float4*)rb1 = *(const float4*)(Bb + (size_t)(k0n + 2 * bkp + 1) * N + bn4);
        }

        // compute on buf p: one k16 step, 16 mmas
        uint32_t af[4][4], bf[4][2];
        #pragma unroll
        for (int mi = 0; mi < 4; mi++) {
            int m0 = wm + mi * 16;
            af[mi][0] = As[p][(m0 + g    ) * GS + tg    ];
            af[mi][1] = As[p][(m0 + g + 8) * GS + tg    ];
            af[mi][2] = As[p][(m0 + g    ) * GS + tg + 4];
            af[mi][3] = As[p][(m0 + g + 8) * GS + tg + 4];
        }
        #pragma unroll
        for (int ni = 0; ni < 4; ni++) {
            int n0 = wn + ni * 8;
            bf[ni][0] = Bs[p][(n0 + g) * GS + tg    ];
            bf[ni][1] = Bs[p][(n0 + g) * GS + tg + 4];
        }
        #pragma unroll
        for (int mi = 0; mi < 4; mi++)
            #pragma unroll
            for (int ni = 0; ni < 4; ni++)
                mma_f16(d[mi][ni], af[mi], bf[ni]);

        if (t + 1 < NT) {             // stage next tile into the other buffer
            #pragma unroll
            for (int u = 0; u < 2; u++) {
                uint2 w;
                w.x = packh2(ra[u].x, ra[u].y);
                w.y = packh2(ra[u].z, ra[u].w);
                *(uint2*)&As[p ^ 1][am[u] * GS + 2 * akc[u]] = w;
            }
            #pragma unroll
            for (int j = 0; j < 4; j++)
                Bs[p ^ 1][(bn4 + j) * GS + bkp] = packh2(rb0[j], rb1[j]);
        }
        __syncthreads();
        p ^= 1;
    }

    // epilogue (C-frag layout identical to validated tf32 path)
    #pragma unroll
    for (int mi = 0; mi < 4; mi++) {
        #pragma unroll
        for (int ni = 0; ni < 4; ni++) {
            int r0 = brow + wm + mi * 16 + g;
            int c  = bcol + wn + ni * 8 + 2 * tg;
            float2 v0, v1;
            v0.x = d[mi][ni][0]; v0.y = d[mi][ni][1];
            v1.x = d[mi][ni][2]; v1.y = d[mi][ni][3];
            if (bias) {
                float2 bb = *(const float2*)(bias + c);
                v0.x += bb.x; v0.y += bb.y;
                v1.x += bb.x; v1.y += bb.y;
            }
            *(float2*)(C + (size_t)r0 * N + c)       = v0;
            *(float2*)(C + (size_t)(r0 + 8) * N + c) = v1;
        }
    }
}

// ============================================================================
// Kernel 2: per-head LayerNorm + RoPE + scatter to [B,H,N,HD].  (unchanged)
// ============================================================================
__global__ __launch_bounds__(256)
void lnrope_kernel(const float* __restrict__ freq,
                   const float* __restrict__ qg, const float* __restrict__ qb,
                   const float* __restrict__ kg, const float* __restrict__ kb)
{
    int warp = (blockIdx.x * blockDim.x + threadIdx.x) >> 5;
    int lane = threadIdx.x & 31;
    const int TOTAL = BATCH * SEQ * HEADS;
    if (warp >= TOTAL) return;

    int h = warp & (HEADS - 1);
    int n = (warp >> 4) & (SEQ - 1);
    int b = warp >> 15;

    const float* src = g_qkv + (size_t)(b * SEQ + n) * QKVC + h * HDIM;
    int d0 = lane * 2;

    float2 q2 = *(const float2*)(src + d0);
    float2 k2 = *(const float2*)(src + DIMC + d0);
    float2 v2 = *(const float2*)(src + 2 * DIMC + d0);

    float sq  = q2.x + q2.y,           sk  = k2.x + k2.y;
    float sq2 = q2.x*q2.x + q2.y*q2.y, sk2 = k2.x*k2.x + k2.y*k2.y;
    #pragma unroll
    for (int off = 16; off; off >>= 1) {
        sq  += __shfl_xor_sync(0xffffffffu, sq,  off);
        sq2 += __shfl_xor_sync(0xffffffffu, sq2, off);
        sk  += __shfl_xor_sync(0xffffffffu, sk,  off);
        sk2 += __shfl_xor_sync(0xffffffffu, sk2, off);
    }
    float qm = sq * (1.f/64.f);
    float qv = sq2 * (1.f/64.f) - qm * qm;
    float qi = rsqrtf(qv + 1e-5f);
    float km = sk * (1.f/64.f);
    float kv = sk2 * (1.f/64.f) - km * km;
    float ki = rsqrtf(kv + 1e-5f);

    float qn0 = (q2.x - qm) * qi * qg[d0]     + qb[d0];
    float qn1 = (q2.y - qm) * qi * qg[d0 + 1] + qb[d0 + 1];
    float kn0 = (k2.x - km) * ki * kg[d0]     + kb[d0];
    float kn1 = (k2.y - km) * ki * kg[d0 + 1] + kb[d0 + 1];

    float co = freq[(n * 32 + lane) * 2 + 0];
    float si = freq[(n * 32 + lane) * 2 + 1];
    float qr = (qn0 * co - qn1 * si) * 0.125f;
    float qe = (qn0 * si + qn1 * co) * 0.125f;
    float kr =  kn0 * co - kn1 * si;
    float ke =  kn0 * si + kn1 * co;

    size_t o = ((size_t)(b * HEADS + h) * SEQ + n) * HDIM + d0;
    *(float2*)(g_q + o) = make_float2(qr, qe);
    *(float2*)(g_k + o) = make_float2(kr, ke);
    *(float2*)(g_v + o) = v2;
}

// ============================================================================
// Kernel 3: flash attention on fp16 tensor cores.
// 128 Q-rows/block, 8 warps x 16-row strips, warp-local softmax.
// K smem: Ks_h2[key][d2] stride 36 (natural layout — fp16 B-frag wants
//   consecutive-d pairs; fragment loads conflict-free: 4g+tg distinct).
// V smem: Vt_h2[d][key2] stride 33 (transposed, key-paired for PV B-frags).
// P stays in registers: S C-frag (c0,c1)/(c2,c3) pairs ARE the fp16 A-frag
//   k-pairs -> pure packh2, zero shuffles. Register prefetch kept from R14.
// ============================================================================
__global__ __launch_bounds__(256)
void attn_mma_kernel()
{
    __shared__ uint32_t Ks[64 * 36];    // h2 [key][d2]
    __shared__ uint32_t Vt[64 * 33];    // h2 [d][key2] (half stride 66)

    int qt  = blockIdx.x;               // 0..15
    int bh  = blockIdx.y;               // 0..31
    int tid = threadIdx.x;
    int warp = tid >> 5, lane = tid & 31;
    int g = lane >> 2, tg = lane & 3;

    const float* Qb = g_q + ((size_t)bh * SEQ + qt * 128 + warp * 16) * HDIM;
    const float* Kb = g_k + (size_t)bh * SEQ * HDIM;
    const float* Vb = g_v + (size_t)bh * SEQ * HDIM;

    // Q fragments (fp16): qf[ki] covers dims ki*16..ki*16+15
    uint32_t qf[4][4];
    #pragma unroll
    for (int ki = 0; ki < 4; ki++) {
        const float* q0 = Qb + g * HDIM + ki * 16;
        const float* q1 = Qb + (g + 8) * HDIM + ki * 16;
        float2 t;
        t = *(const float2*)(q0 + 2 * tg);     qf[ki][0] = packh2(t.x, t.y);
        t = *(const float2*)(q1 + 2 * tg);     qf[ki][1] = packh2(t.x, t.y);
        t = *(const float2*)(q0 + 2 * tg + 8); qf[ki][2] = packh2(t.x, t.y);
        t = *(const float2*)(q1 + 2 * tg + 8); qf[ki][3] = packh2(t.x, t.y);
    }

    float oc[8][4];
    #pragma unroll
    for (int ni = 0; ni < 8; ni++)
        #pragma unroll
        for (int r = 0; r < 4; r++) oc[ni][r] = 0.f;
    float m0 = -INFINITY, m1 = -INFINITY, l0 = 0.f, l1 = 0.f;

    // prologue: tile 0 into registers
    float4 pk[4], pv[4];
    #pragma unroll
    for (int u = 0; u < 4; u++) {
        int i  = tid + u * 256;
        int r  = i >> 4;
        int d4 = (i & 15) * 4;
        pk[u] = *(const float4*)(Kb + (size_t)r * HDIM + d4);
        pv[u] = *(const float4*)(Vb + (size_t)r * HDIM + d4);
    }

    for (int kt = 0; kt < SEQ / 64; kt++) {
        // ---- stage prefetched regs -> smem (fp16 convert) ----
        #pragma unroll
        for (int u = 0; u < 4; u++) {
            int i  = tid + u * 256;
            int r  = i >> 4;             // key
            int d4 = (i & 15) * 4;
            uint2 kw;
            kw.x = packh2(pk[u].x, pk[u].y);
            kw.y = packh2(pk[u].z, pk[u].w);
            *(uint2*)&Ks[r * 36 + (d4 >> 1)] = kw;
            __half* vh = (__half*)Vt;    // transposed, key-major halves
            vh[(d4 + 0) * 66 + r] = __float2half_rn(pv[u].x);
            vh[(d4 + 1) * 66 + r] = __float2half_rn(pv[u].y);
            vh[(d4 + 2) * 66 + r] = __float2half_rn(pv[u].z);
            vh[(d4 + 3) * 66 + r] = __float2half_rn(pv[u].w);
        }
        __syncthreads();   // publish tile kt

        // ---- prefetch tile kt+1 ----
        if (kt + 1 < SEQ / 64) {
            #pragma unroll
            for (int u = 0; u < 4; u++) {
                int i  = tid + u * 256;
                int r  = (kt + 1) * 64 + (i >> 4);
                int d4 = (i & 15) * 4;
                pk[u] = *(const float4*)(Kb + (size_t)r * HDIM + d4);
                pv[u] = *(const float4*)(Vb + (size_t)r * HDIM + d4);
            }
        }

        // ---- S = Q @ K^T (4 k16 chunks x 8 key-blocks) ----
        float sc[8][4];
        #pragma unroll
        for (int ni = 0; ni < 8; ni++)
            #pragma unroll
            for (int r = 0; r < 4; r++) sc[ni][r] = 0.f;
        #pragma unroll
        for (int ki = 0; ki < 4; ki++) {
            #pragma unroll
            for (int ni = 0; ni < 8; ni++) {
                uint32_t b[2];
                b[0] = Ks[(ni * 8 + g) * 36 + ki * 8 + tg    ];
                b[1] = Ks[(ni * 8 + g) * 36 + ki * 8 + tg + 4];
                mma_f16(sc[ni], qf[ki], b);
            }
        }

        // ---- online softmax + pack P straight into fp16 A-frags ----
        float mx0 = -INFINITY, mx1 = -INFINITY;
        #pragma unroll
        for (int ni = 0; ni < 8; ni++) {
            mx0 = fmaxf(mx0, fmaxf(sc[ni][0], sc[ni][1]));
            mx1 = fmaxf(mx1, fmaxf(sc[ni][2], sc[ni][3]));
        }
        mx0 = fmaxf(mx0, __shfl_xor_sync(0xffffffffu, mx0, 1));
        mx0 = fmaxf(mx0, __shfl_xor_sync(0xffffffffu, mx0, 2));
        mx1 = fmaxf(mx1, __shfl_xor_sync(0xffffffffu, mx1, 1));
        mx1 = fmaxf(mx1, __shfl_xor_sync(0xffffffffu, mx1, 2));

        float mn0 = fmaxf(m0, mx0), mn1 = fmaxf(m1, mx1);
        float a0 = __expf(m0 - mn0), a1 = __expf(m1 - mn1);

        uint32_t pa[4][4];
        float s0 = 0.f, s1 = 0.f;
        #pragma unroll
        for (int ni = 0; ni < 8; ni++) {
            float p0 = __expf(sc[ni][0] - mn0);
            float p1 = __expf(sc[ni][1] - mn0);
            float p2 = __expf(sc[ni][2] - mn1);
            float p3 = __expf(sc[ni][3] - mn1);
            s0 += p0 + p1; s1 += p2 + p3;
            int ki = ni >> 1;
            if (ni & 1) { pa[ki][2] = packh2(p0, p1); pa[ki][3] = packh2(p2, p3); }
            else        { pa[ki][0] = packh2(p0, p1); pa[ki][1] = packh2(p2, p3); }
        }
        s0 += __shfl_xor_sync(0xffffffffu, s0, 1);
        s0 += __shfl_xor_sync(0xffffffffu, s0, 2);
        s1 += __shfl_xor_sync(0xffffffffu, s1, 1);
        s1 += __shfl_xor_sync(0xffffffffu, s1, 2);

        l0 = a0 * l0 + s0;  l1 = a1 * l1 + s1;
        m0 = mn0;           m1 = mn1;
        #pragma unroll
        for (int ni = 0; ni < 8; ni++) {
            oc[ni][0] *= a0; oc[ni][1] *= a0;
            oc[ni][2] *= a1; oc[ni][3] *= a1;
        }

        // ---- O += P @ V (4 key-chunks x 8 d-blocks) ----
        #pragma unroll
        for (int ki = 0; ki < 4; ki++) {
            #pragma unroll
            for (int ni = 0; ni < 8; ni++) {
                uint32_t b[2];
                b[0] = Vt[(ni * 8 + g) * 33 + ki * 8 + tg    ];
                b[1] = Vt[(ni * 8 + g) * 33 + ki * 8 + tg + 4];
                mma_f16(oc[ni], pa[ki], b);
            }
        }
        __syncthreads();   // reads of Ks/Vt done before next store phase
    }

    // ---- epilogue: normalize, write [B, N, DIM] ----
    int b = bh >> 4, h = bh & 15;
    int row0 = qt * 128 + warp * 16 + g;
    float i0 = 1.f / l0, i1 = 1.f / l1;
    #pragma unroll
    for (int ni = 0; ni < 8; ni++) {
        int d = h * HDIM + ni * 8 + 2 * tg;
        float2 v;
        v.x = oc[ni][0] * i0; v.y = oc[ni][1] * i0;
        *(float2*)(g_attn + (size_t)(b * SEQ + row0) * DIMC + d) = v;
        v.x = oc[ni][2] * i1; v.y = oc[ni][3] * i1;
        *(float2*)(g_attn + (size_t)(b * SEQ + row0 + 8) * DIMC + d) = v;
    }
}

// ============================================================================
// launch
// ============================================================================
extern "C" void kernel_launch(void* const* d_in, const int* in_sizes, int n_in,
                              void* d_out, int out_size)
{
    const float* x    = (const float*)d_in[0];
    const float* freq = (const float*)d_in[1];
    const float* Wqkv = (const float*)d_in[2];
    const float* qg   = (const float*)d_in[3];
    const float* qb   = (const float*)d_in[4];
    const float* kg   = (const float*)d_in[5];
    const float* kb   = (const float*)d_in[6];
    const float* Wp   = (const float*)d_in[7];
    const float* bp   = (const float*)d_in[8];
    float* out = (float*)d_out;

    float *qkv_p = nullptr, *attn_p = nullptr;
    cudaGetSymbolAddress((void**)&qkv_p,  g_qkv);
    cudaGetSymbolAddress((void**)&attn_p, g_attn);

    // 1. qkv = x @ Wqkv          [4096,1024] @ [1024,3072]  (fp16 mma)
    {
        dim3 grid(QKVC / 128, ROWS / 128);
        mma_gemm_kernel<<<grid, 256>>>(x, Wqkv, qkv_p, ROWS, QKVC, DIMC, nullptr);
    }
    // 2. LN + RoPE + scatter to [B,H,N,HD] (Q pre-scaled by 1/8)
    {
        int warps = BATCH * SEQ * HEADS;
        lnrope_kernel<<<warps / 8, 256>>>(freq, qg, qb, kg, kb);
    }
    // 3. flash attention (fp16 mma) -> g_attn [B,N,DIM]
    {
        dim3 grid(SEQ / 128, BATCH * HEADS);
        attn_mma_kernel<<<grid, 256>>>();
    }
    // 4. out = attn @ Wproj + bproj   [4096,1024] @ [1024,1024]  (fp16 mma)
    {
        dim3 grid(DIMC / 128, ROWS / 128);
        mma_gemm_kernel<<<grid, 256>>>(attn_p, Wp, out, ROWS, DIMC, DIMC, bp);
    }
}